// round 1
// baseline (speedup 1.0000x reference)
#include <cuda_runtime.h>
#include <math.h>

// Problem constants
#define NN   50000
#define FF   500
#define EE   1600000
#define PEE  400000
#define HH1  128
#define HH2  64

// Output layout (floats): res[800000] | lsm[150000] | att[150000] | feat[3200000]
#define OUT_RES  0
#define OUT_LSM  800000
#define OUT_ATT  950000
#define OUT_FEAT 1100000

// Scratch (static __device__ arrays; allocation-free per harness rules)
__device__ float g_dinv[NN];
__device__ float g_gW1[FF * HH1];
__device__ float g_h1pre[NN * HH1];
__device__ float g_h1[NN * HH1];
__device__ float g_h2pre[NN * HH2];
__device__ float g_headpre[NN * 6];
__device__ float g_attrall[NN * 6];

// ---------------------------------------------------------------------------
// Vector reductions to global memory (sm_90+)
__device__ __forceinline__ void red_add_v4(float* p, float4 v) {
    asm volatile("red.global.add.v4.f32 [%0], {%1,%2,%3,%4};"
                 :: "l"(p), "f"(v.x), "f"(v.y), "f"(v.z), "f"(v.w) : "memory");
}
__device__ __forceinline__ void red_add_v2(float* p, float a, float b) {
    asm volatile("red.global.add.v2.f32 [%0], {%1,%2};"
                 :: "l"(p), "f"(a), "f"(b) : "memory");
}

// ---------------------------------------------------------------------------
// gW1 = glove @ W1   [FF x FF] @ [FF x HH1]
__global__ void k_glove_w1(const float* __restrict__ glove,
                           const float* __restrict__ W1,
                           float* __restrict__ gW1) {
    __shared__ float row[FF];
    int k = blockIdx.x;
    for (int f = threadIdx.x; f < FF; f += blockDim.x) row[f] = glove[k * FF + f];
    __syncthreads();
    int j = threadIdx.x;  // 128 threads
    float acc = 0.f;
    #pragma unroll 4
    for (int f = 0; f < FF; f++) acc += row[f] * __ldg(&W1[f * HH1 + j]);
    gW1[k * HH1 + j] = acc;
}

// ---------------------------------------------------------------------------
// Degree / normalization
__global__ void k_deg_init(float* deg) {
    int i = blockIdx.x * blockDim.x + threadIdx.x;
    if (i < NN) deg[i] = 1.0f;  // self loop
}
__global__ void k_deg_acc(const int* __restrict__ dst, float* deg) {
    int e = blockIdx.x * blockDim.x + threadIdx.x;
    if (e < EE) atomicAdd(&deg[dst[e]], 1.0f);
}
__global__ void k_dinv(float* deg) {
    int i = blockIdx.x * blockDim.x + threadIdx.x;
    if (i < NN) deg[i] = rsqrtf(deg[i]);
}

// ---------------------------------------------------------------------------
// Tiled SGEMM: C[M,BN] = A[M,K] @ B[K,BN], optional ReLU applied to A on load.
// BM=64, BK=16, 256 threads. Requires K % 4 == 0 and 16B-aligned rows.
template <int BN, int TM, int TN, bool RELU>
__global__ void k_sgemm(const float* __restrict__ A, const float* __restrict__ B,
                        float* __restrict__ C, int M, int K) {
    constexpr int BM = 64, BK = 16;
    constexpr int TX = BN / TN;
    __shared__ float As[BK][BM];
    __shared__ float Bs[BK][BN];
    int tid = threadIdx.x;
    int tx = tid % TX, ty = tid / TX;
    int m0 = blockIdx.x * BM;

    float acc[TM][TN];
    #pragma unroll
    for (int i = 0; i < TM; i++)
        #pragma unroll
        for (int j = 0; j < TN; j++) acc[i][j] = 0.f;

    int ar = tid >> 2;           // 0..63
    int ac = (tid & 3) * 4;      // 0,4,8,12

    for (int k0 = 0; k0 < K; k0 += BK) {
        // Load A tile (transposed into shared)
        float4 av = make_float4(0.f, 0.f, 0.f, 0.f);
        int gr = m0 + ar;
        if (gr < M && (k0 + ac) < K)
            av = *(const float4*)(A + (long)gr * K + k0 + ac);
        if (RELU) {
            av.x = fmaxf(av.x, 0.f); av.y = fmaxf(av.y, 0.f);
            av.z = fmaxf(av.z, 0.f); av.w = fmaxf(av.w, 0.f);
        }
        As[ac + 0][ar] = av.x; As[ac + 1][ar] = av.y;
        As[ac + 2][ar] = av.z; As[ac + 3][ar] = av.w;
        // Load B tile
        if (BN == 128) {
            int br = tid >> 5, bc = (tid & 31) * 4;
            #pragma unroll
            for (int r = 0; r < 2; r++) {
                float4 bv = make_float4(0.f, 0.f, 0.f, 0.f);
                int kk = k0 + br + r * 8;
                if (kk < K) bv = *(const float4*)(B + (long)kk * BN + bc);
                *(float4*)&Bs[br + r * 8][bc] = bv;
            }
        } else {
            int br = tid >> 4, bc = (tid & 15) * 4;
            float4 bv = make_float4(0.f, 0.f, 0.f, 0.f);
            int kk = k0 + br;
            if (kk < K) bv = *(const float4*)(B + (long)kk * BN + bc);
            *(float4*)&Bs[br][bc] = bv;
        }
        __syncthreads();
        #pragma unroll
        for (int k = 0; k < BK; k++) {
            float ra[TM], rb[TN];
            #pragma unroll
            for (int i = 0; i < TM; i++) ra[i] = As[k][ty * TM + i];
            #pragma unroll
            for (int j = 0; j < TN; j++) rb[j] = Bs[k][tx * TN + j];
            #pragma unroll
            for (int i = 0; i < TM; i++)
                #pragma unroll
                for (int j = 0; j < TN; j++) acc[i][j] += ra[i] * rb[j];
        }
        __syncthreads();
    }
    #pragma unroll
    for (int i = 0; i < TM; i++) {
        int r = m0 + ty * TM + i;
        if (r < M) {
            #pragma unroll
            for (int j = 0; j < TN; j += 4) {
                float4 v = make_float4(acc[i][j], acc[i][j+1], acc[i][j+2], acc[i][j+3]);
                *(float4*)(C + (long)r * BN + tx * TN + j) = v;
            }
        }
    }
}

// ---------------------------------------------------------------------------
// init: out[i,:] = bias + dinv[i]^2 * pre[i,:]   (self-loop folded in), DIM%4==0
template <int DIM>
__global__ void k_init_bias_self(const float* __restrict__ pre,
                                 const float* __restrict__ bias,
                                 const float* __restrict__ dinv,
                                 float* __restrict__ out) {
    int t = blockIdx.x * blockDim.x + threadIdx.x;   // N * DIM/4 threads
    constexpr int V = DIM / 4;
    int i = t / V, c = (t % V) * 4;
    if (i >= NN) return;
    float w = dinv[i]; w *= w;
    float4 p = *(const float4*)(pre + (long)i * DIM + c);
    float4 b = *(const float4*)(bias + c);
    float4 o;
    o.x = b.x + w * p.x; o.y = b.y + w * p.y;
    o.z = b.z + w * p.z; o.w = b.w + w * p.w;
    *(float4*)(out + (long)i * DIM + c) = o;
}

// scatter: out[d,:] += dinv[s]*dinv[d] * pre[s,:]  for DIM=128 (warp/edge) ----
__global__ void k_scatter128(const float* __restrict__ pre,
                             const int* __restrict__ src, const int* __restrict__ dst,
                             const float* __restrict__ dinv, float* __restrict__ out) {
    int t = blockIdx.x * blockDim.x + threadIdx.x;
    int e = t >> 5, lane = t & 31;
    if (e >= EE) return;
    int s = __ldg(src + e), d = __ldg(dst + e);
    float w = __ldg(dinv + s) * __ldg(dinv + d);
    float4 v = __ldg((const float4*)(pre + (long)s * 128) + lane);
    v.x *= w; v.y *= w; v.z *= w; v.w *= w;
    red_add_v4(out + (long)d * 128 + lane * 4, v);
}

// DIM=64: 16 lanes/edge
__global__ void k_scatter64(const float* __restrict__ pre,
                            const int* __restrict__ src, const int* __restrict__ dst,
                            const float* __restrict__ dinv, float* __restrict__ out) {
    int t = blockIdx.x * blockDim.x + threadIdx.x;
    int e = t >> 4, lane = t & 15;
    if (e >= EE) return;
    int s = __ldg(src + e), d = __ldg(dst + e);
    float w = __ldg(dinv + s) * __ldg(dinv + d);
    float4 v = __ldg((const float4*)(pre + (long)s * 64) + lane);
    v.x *= w; v.y *= w; v.z *= w; v.w *= w;
    red_add_v4(out + (long)d * 64 + lane * 4, v);
}

// DIM=6 (both heads fused): 1 thread/edge, 3x red.v2
__global__ void k_scatter6(const float* __restrict__ pre,
                           const int* __restrict__ src, const int* __restrict__ dst,
                           const float* __restrict__ dinv, float* __restrict__ out) {
    int e = blockIdx.x * blockDim.x + threadIdx.x;
    if (e >= EE) return;
    int s = __ldg(src + e), d = __ldg(dst + e);
    float w = __ldg(dinv + s) * __ldg(dinv + d);
    const float2* p = (const float2*)(pre + (long)s * 6);
    float* o = out + (long)d * 6;
    float2 a = __ldg(p), b = __ldg(p + 1), c = __ldg(p + 2);
    red_add_v2(o,     a.x * w, a.y * w);
    red_add_v2(o + 2, b.x * w, b.y * w);
    red_add_v2(o + 4, c.x * w, c.y * w);
}

// ---------------------------------------------------------------------------
// headpre[i, 0:3] = feat[i,:] @ W_attr ; headpre[i, 3:6] = feat[i,:] @ W_attk
__global__ void k_heads_gemm(const float* __restrict__ feat,
                             const float* __restrict__ W_attr,
                             const float* __restrict__ W_attk,
                             float* __restrict__ headpre) {
    __shared__ float Ws[HH2 * 6];
    for (int t = threadIdx.x; t < HH2 * 6; t += blockDim.x) {
        int k = t / 6, c = t % 6;
        Ws[t] = (c < 3) ? W_attr[k * 3 + c] : W_attk[k * 3 + (c - 3)];
    }
    __syncthreads();
    int i = blockIdx.x * blockDim.x + threadIdx.x;
    if (i >= NN) return;
    float acc[6] = {0.f, 0.f, 0.f, 0.f, 0.f, 0.f};
    const float4* row = (const float4*)(feat + (long)i * HH2);
    #pragma unroll
    for (int q = 0; q < 16; q++) {
        float4 v = __ldg(row + q);
        float vv[4] = {v.x, v.y, v.z, v.w};
        #pragma unroll
        for (int u = 0; u < 4; u++) {
            int k = q * 4 + u;
            #pragma unroll
            for (int c = 0; c < 6; c++) acc[c] += vv[u] * Ws[k * 6 + c];
        }
    }
    #pragma unroll
    for (int c = 0; c < 6; c++) headpre[(long)i * 6 + c] = acc[c];
}

// init heads: attrall[i,:] = [b_attr|b_attk] + dinv^2 * headpre[i,:]
__global__ void k_init_heads(const float* __restrict__ headpre,
                             const float* __restrict__ b_attr,
                             const float* __restrict__ b_attk,
                             const float* __restrict__ dinv,
                             float* __restrict__ attrall) {
    int t = blockIdx.x * blockDim.x + threadIdx.x;
    int i = t / 6, c = t % 6;
    if (i >= NN) return;
    float w = dinv[i]; w *= w;
    float b = (c < 3) ? b_attr[c] : b_attk[c - 3];
    attrall[t] = b + w * headpre[t];
}

// finalize: log_softmax(attr) -> lsm region, attk -> att region
__global__ void k_finalize(const float* __restrict__ attrall, float* __restrict__ out) {
    int i = blockIdx.x * blockDim.x + threadIdx.x;
    if (i >= NN) return;
    float a0 = attrall[i * 6 + 0], a1 = attrall[i * 6 + 1], a2 = attrall[i * 6 + 2];
    float m = fmaxf(a0, fmaxf(a1, a2));
    float l = m + logf(expf(a0 - m) + expf(a1 - m) + expf(a2 - m));
    out[OUT_LSM + i * 3 + 0] = a0 - l;
    out[OUT_LSM + i * 3 + 1] = a1 - l;
    out[OUT_LSM + i * 3 + 2] = a2 - l;
    out[OUT_ATT + i * 3 + 0] = attrall[i * 6 + 3];
    out[OUT_ATT + i * 3 + 1] = attrall[i * 6 + 4];
    out[OUT_ATT + i * 3 + 2] = attrall[i * 6 + 5];
}

// edge scores: res[e] = dot(feat[tot1[e]], feat[tot0[e]]), 8 lanes/edge
__global__ void k_edge_scores(const float* __restrict__ feat,
                              const int* __restrict__ pos,   // [2, PEE]
                              const int* __restrict__ neg,   // [2, PEE]
                              float* __restrict__ res) {
    int t = blockIdx.x * blockDim.x + threadIdx.x;
    int e = t >> 3, l = t & 7;
    if (e >= 2 * PEE) return;
    int a, b;
    if (e < PEE) { a = __ldg(pos + e); b = __ldg(pos + PEE + e); }
    else         { a = __ldg(neg + (e - PEE)); b = __ldg(neg + PEE + (e - PEE)); }
    const float4* fa = (const float4*)(feat + (long)a * 64);
    const float4* fb = (const float4*)(feat + (long)b * 64);
    float4 u = __ldg(fa + l), v = __ldg(fb + l);
    float s = u.x * v.x + u.y * v.y + u.z * v.z + u.w * v.w;
    u = __ldg(fa + l + 8); v = __ldg(fb + l + 8);
    s += u.x * v.x + u.y * v.y + u.z * v.z + u.w * v.w;
    s += __shfl_down_sync(0xffffffffu, s, 4, 8);
    s += __shfl_down_sync(0xffffffffu, s, 2, 8);
    s += __shfl_down_sync(0xffffffffu, s, 1, 8);
    if (l == 0) res[e] = s;
}

// ---------------------------------------------------------------------------
static inline int cdiv(long a, int b) { return (int)((a + b - 1) / b); }

extern "C" void kernel_launch(void* const* d_in, const int* in_sizes, int n_in,
                              void* d_out, int out_size) {
    const float* x      = (const float*)d_in[0];
    const float* glove  = (const float*)d_in[1];
    const float* W1     = (const float*)d_in[2];
    const float* b1     = (const float*)d_in[3];
    const float* W2     = (const float*)d_in[4];
    const float* b2     = (const float*)d_in[5];
    const float* W_attr = (const float*)d_in[6];
    const float* b_attr = (const float*)d_in[7];
    const float* W_attk = (const float*)d_in[8];
    const float* b_attk = (const float*)d_in[9];
    const int* edge     = (const int*)d_in[10];   // [2, EE]
    const int* pos      = (const int*)d_in[11];   // [2, PEE]
    const int* neg      = (const int*)d_in[12];   // [2, PEE]
    float* out = (float*)d_out;

    const int* e_src = edge;
    const int* e_dst = edge + EE;

    float *dinv, *gW1, *h1pre, *h1, *h2pre, *headpre, *attrall;
    cudaGetSymbolAddress((void**)&dinv,    g_dinv);
    cudaGetSymbolAddress((void**)&gW1,     g_gW1);
    cudaGetSymbolAddress((void**)&h1pre,   g_h1pre);
    cudaGetSymbolAddress((void**)&h1,      g_h1);
    cudaGetSymbolAddress((void**)&h2pre,   g_h2pre);
    cudaGetSymbolAddress((void**)&headpre, g_headpre);
    cudaGetSymbolAddress((void**)&attrall, g_attrall);

    // 1) gW1 = glove @ W1 (identity-glove folds to W1 exactly)
    k_glove_w1<<<FF, HH1>>>(glove, W1, gW1);

    // 2) normalization
    k_deg_init<<<cdiv(NN, 256), 256>>>(dinv);
    k_deg_acc<<<cdiv(EE, 256), 256>>>(e_dst, dinv);
    k_dinv<<<cdiv(NN, 256), 256>>>(dinv);

    // 3) h1pre = x @ gW1
    k_sgemm<128, 8, 4, false><<<cdiv(NN, 64), 256>>>(x, gW1, h1pre, NN, FF);

    // 4) layer1 aggregate: h1 = b1 + self + scatter  (ReLU fused into GEMM2 load)
    k_init_bias_self<128><<<cdiv((long)NN * 32, 256), 256>>>(h1pre, b1, dinv, h1);
    k_scatter128<<<cdiv((long)EE * 32, 256), 256>>>(h1pre, e_src, e_dst, dinv, h1);

    // 5) h2pre = relu(h1) @ W2
    k_sgemm<64, 4, 4, true><<<cdiv(NN, 64), 256>>>(h1, W2, h2pre, NN, HH1);

    // 6) layer2 aggregate -> feat region of d_out
    float* feat = out + OUT_FEAT;
    k_init_bias_self<64><<<cdiv((long)NN * 16, 256), 256>>>(h2pre, b2, dinv, feat);
    k_scatter64<<<cdiv((long)EE * 16, 256), 256>>>(h2pre, e_src, e_dst, dinv, feat);

    // 7) both heads fused: headpre = feat @ [W_attr | W_attk]
    k_heads_gemm<<<cdiv(NN, 128), 128>>>(feat, W_attr, W_attk, headpre);
    k_init_heads<<<cdiv((long)NN * 6, 256), 256>>>(headpre, b_attr, b_attk, dinv, attrall);
    k_scatter6<<<cdiv(EE, 256), 256>>>(headpre, e_src, e_dst, dinv, attrall);

    // 8) log_softmax + att outputs
    k_finalize<<<cdiv(NN, 256), 256>>>(attrall, out);

    // 9) edge dot-product scores
    k_edge_scores<<<cdiv((long)2 * PEE * 8, 256), 256>>>(feat, pos, neg, out + OUT_RES);
}

// round 6
// speedup vs baseline: 1.6850x; 1.6850x over previous
#include <cuda_runtime.h>
#include <cuda_bf16.h>
#include <math.h>

// Problem constants
#define NN   50000
#define FF   500
#define EE   1600000
#define PEE  400000
#define HH1  128
#define HH2  64

// Output layout (floats): res[800000] | lsm[150000] | att[150000] | feat[3200000]
#define OUT_RES  0
#define OUT_LSM  800000
#define OUT_ATT  950000
#define OUT_FEAT 1100000

#define KPAD1 512   // 500 padded
#define KPAD2 128

// ---------------------------------------------------------------------------
// Scratch (static __device__ arrays; allocation-free per harness rules)
__device__ int   g_degi[NN];
__device__ float g_dinv[NN];
__device__ int   g_off[NN + 1];
__device__ int   g_cursor[NN];
__device__ int   g_csr_src[EE];
__device__ float g_gW1[FF * HH1];
__device__ __nv_bfloat16 g_W1hT[HH1 * KPAD1];
__device__ __nv_bfloat16 g_W1lT[HH1 * KPAD1];
__device__ __nv_bfloat16 g_W2hT[HH2 * KPAD2];
__device__ __nv_bfloat16 g_W2lT[HH2 * KPAD2];
__device__ float g_h1pre[NN * HH1];
__device__ float g_h1[NN * HH1];
__device__ float g_h2pre[NN * HH2];
__device__ float g_headpre[NN * 6];

// ---------------------------------------------------------------------------
__device__ __forceinline__ unsigned pack_bf16(float a, float b) {
    __nv_bfloat162 h = __floats2bfloat162_rn(a, b);
    return *(unsigned*)&h;
}
__device__ __forceinline__ float bf_hi(float v) {
    return __bfloat162float(__float2bfloat16(v));
}
__device__ __forceinline__ void mma16816(float* d, const unsigned* a,
                                         unsigned b0, unsigned b1) {
    asm volatile(
        "mma.sync.aligned.m16n8k16.row.col.f32.bf16.bf16.f32 "
        "{%0,%1,%2,%3},{%4,%5,%6,%7},{%8,%9},{%0,%1,%2,%3};\n"
        : "+f"(d[0]), "+f"(d[1]), "+f"(d[2]), "+f"(d[3])
        : "r"(a[0]), "r"(a[1]), "r"(a[2]), "r"(a[3]), "r"(b0), "r"(b1));
}

// ---------------------------------------------------------------------------
// gW1 = glove @ W1   [FF x FF] @ [FF x HH1]
__global__ void k_glove_w1(const float* __restrict__ glove,
                           const float* __restrict__ W1,
                           float* __restrict__ gW1) {
    __shared__ float row[FF];
    int k = blockIdx.x;
    for (int f = threadIdx.x; f < FF; f += blockDim.x) row[f] = glove[k * FF + f];
    __syncthreads();
    int j = threadIdx.x;  // 128 threads
    float acc = 0.f;
    #pragma unroll 4
    for (int f = 0; f < FF; f++) acc += row[f] * __ldg(&W1[f * HH1 + j]);
    gW1[k * HH1 + j] = acc;
}

// Split weight W[KS x N] into transposed bf16 hi/lo [N x KP] (zero padded)
template <int KS, int KP, int NW>
__global__ void k_splitW(const float* __restrict__ W,
                         __nv_bfloat16* __restrict__ WhT,
                         __nv_bfloat16* __restrict__ WlT) {
    int idx = blockIdx.x * blockDim.x + threadIdx.x;
    if (idx >= NW * KP) return;
    int n = idx / KP, k = idx % KP;
    float v = (k < KS) ? __ldg(&W[(long)k * NW + n]) : 0.f;
    float h = bf_hi(v);
    WhT[idx] = __float2bfloat16(h);
    WlT[idx] = __float2bfloat16(v - h);
}

// ---------------------------------------------------------------------------
// degree / norm / CSR build
__global__ void k_deg_acc(const int* __restrict__ dst, int* __restrict__ degi) {
    int e = blockIdx.x * blockDim.x + threadIdx.x;
    if (e < EE) atomicAdd(&degi[dst[e]], 1);
}
__global__ void k_dinv(const int* __restrict__ degi, float* __restrict__ dinv) {
    int i = blockIdx.x * blockDim.x + threadIdx.x;
    if (i < NN) dinv[i] = rsqrtf((float)degi[i] + 1.0f);  // +1 self loop
}
// exclusive prefix sum over degi -> off[0..NN], also copy into cursor
__global__ void k_scan(const int* __restrict__ degi, int* __restrict__ off,
                       int* __restrict__ cursor) {
    __shared__ int warp_sums[32];
    __shared__ int s_carry;
    int tid = threadIdx.x, lane = tid & 31, wid = tid >> 5;
    if (tid == 0) s_carry = 0;
    __syncthreads();
    for (int base = 0; base < NN; base += 1024) {
        int idx = base + tid;
        int v = (idx < NN) ? degi[idx] : 0;
        int x = v;
        #pragma unroll
        for (int o = 1; o < 32; o <<= 1) {
            int y = __shfl_up_sync(0xffffffffu, x, o);
            if (lane >= o) x += y;
        }
        if (lane == 31) warp_sums[wid] = x;
        __syncthreads();
        if (wid == 0) {
            int s = warp_sums[lane];
            #pragma unroll
            for (int o = 1; o < 32; o <<= 1) {
                int y = __shfl_up_sync(0xffffffffu, s, o);
                if (lane >= o) s += y;
            }
            warp_sums[lane] = s;
        }
        __syncthreads();
        int carry = s_carry;
        int woff = wid ? warp_sums[wid - 1] : 0;
        int excl = carry + woff + (x - v);
        if (idx < NN) { off[idx] = excl; cursor[idx] = excl; }
        __syncthreads();
        if (tid == 0) s_carry = carry + warp_sums[31];
        __syncthreads();
    }
    if (threadIdx.x == 0) off[NN] = s_carry;
}
__global__ void k_fill(const int* __restrict__ src, const int* __restrict__ dst,
                       int* __restrict__ cursor, int* __restrict__ csr_src) {
    int e = blockIdx.x * blockDim.x + threadIdx.x;
    if (e >= EE) return;
    int d = dst[e];
    int p = atomicAdd(&cursor[d], 1);
    csr_src[p] = src[e];
}

// ---------------------------------------------------------------------------
// bf16-split tensor GEMM: C[M x BN] = A[M x KSRC] @ B (split hi/lo, [BN x KP])
// BM=128, BK=32, 256 threads (8 warps, 4x2 warp grid). RELU applied to A on load.
template <int BN, int KSRC, int KP, bool RELU>
__global__ void __launch_bounds__(256)
k_mma(const float* __restrict__ A,
      const __nv_bfloat16* __restrict__ BhT, const __nv_bfloat16* __restrict__ BlT,
      float* __restrict__ C, int M) {
    constexpr int BM = 128, BK = 32, BKP = 40;
    constexpr int WN = (BN == 128) ? 64 : 32;
    constexpr int NF = WN / 8;
    __shared__ __nv_bfloat16 Ah[BM][BKP], Al[BM][BKP];
    __shared__ __nv_bfloat16 Bh[BN][BKP], Bl[BN][BKP];

    int tid = threadIdx.x;
    int m0 = blockIdx.x * BM;
    int lane = tid & 31, w = tid >> 5;
    int wm = (w >> 1) * 32, wn = (w & 1) * WN;
    int g = lane >> 2, tg = lane & 3;

    float acc[2][NF][4];
    #pragma unroll
    for (int mi = 0; mi < 2; mi++)
        #pragma unroll
        for (int ni = 0; ni < NF; ni++)
            #pragma unroll
            for (int q = 0; q < 4; q++) acc[mi][ni][q] = 0.f;

    int ar = tid >> 1;
    int ac0 = (tid & 1) * 16;
    long gr = m0 + ar;
    const float4* ap = (const float4*)(A + gr * (long)KSRC);

    for (int kc = 0; kc < KP; kc += BK) {
        // --- stage A tile: fp32 load -> hi/lo bf16 split ---
        #pragma unroll
        for (int j = 0; j < 4; j++) {
            int c = kc + ac0 + j * 4;
            float4 v = make_float4(0.f, 0.f, 0.f, 0.f);
            if (gr < M && c < KSRC) v = __ldg(ap + (c >> 2));
            if (RELU) {
                v.x = fmaxf(v.x, 0.f); v.y = fmaxf(v.y, 0.f);
                v.z = fmaxf(v.z, 0.f); v.w = fmaxf(v.w, 0.f);
            }
            float h0 = bf_hi(v.x), h1 = bf_hi(v.y), h2 = bf_hi(v.z), h3 = bf_hi(v.w);
            int lc = ac0 + j * 4;
            *(unsigned*)&Ah[ar][lc]     = pack_bf16(h0, h1);
            *(unsigned*)&Ah[ar][lc + 2] = pack_bf16(h2, h3);
            *(unsigned*)&Al[ar][lc]     = pack_bf16(v.x - h0, v.y - h1);
            *(unsigned*)&Al[ar][lc + 2] = pack_bf16(v.z - h2, v.w - h3);
        }
        // --- stage B tiles (already bf16, [n][k] layout) ---
        for (int idx = tid; idx < BN * 4; idx += 256) {
            int n = idx >> 2, ko = (idx & 3) * 8;
            *(uint4*)&Bh[n][ko] = __ldg((const uint4*)(BhT + (long)n * KP + kc + ko));
            *(uint4*)&Bl[n][ko] = __ldg((const uint4*)(BlT + (long)n * KP + kc + ko));
        }
        __syncthreads();
        // --- compute ---
        #pragma unroll
        for (int ks = 0; ks < 2; ks++) {
            int kb = ks * 16;
            unsigned ah[2][4], al[2][4];
            #pragma unroll
            for (int mi = 0; mi < 2; mi++) {
                int r0 = wm + mi * 16 + g;
                ah[mi][0] = *(const unsigned*)&Ah[r0][kb + 2 * tg];
                ah[mi][1] = *(const unsigned*)&Ah[r0 + 8][kb + 2 * tg];
                ah[mi][2] = *(const unsigned*)&Ah[r0][kb + 2 * tg + 8];
                ah[mi][3] = *(const unsigned*)&Ah[r0 + 8][kb + 2 * tg + 8];
                al[mi][0] = *(const unsigned*)&Al[r0][kb + 2 * tg];
                al[mi][1] = *(const unsigned*)&Al[r0 + 8][kb + 2 * tg];
                al[mi][2] = *(const unsigned*)&Al[r0][kb + 2 * tg + 8];
                al[mi][3] = *(const unsigned*)&Al[r0 + 8][kb + 2 * tg + 8];
            }
            #pragma unroll
            for (int ni = 0; ni < NF; ni++) {
                int bn = wn + ni * 8 + g;
                unsigned bh0 = *(const unsigned*)&Bh[bn][kb + 2 * tg];
                unsigned bh1 = *(const unsigned*)&Bh[bn][kb + 2 * tg + 8];
                unsigned bl0 = *(const unsigned*)&Bl[bn][kb + 2 * tg];
                unsigned bl1 = *(const unsigned*)&Bl[bn][kb + 2 * tg + 8];
                #pragma unroll
                for (int mi = 0; mi < 2; mi++) {
                    mma16816(acc[mi][ni], ah[mi], bh0, bh1);
                    mma16816(acc[mi][ni], ah[mi], bl0, bl1);
                    mma16816(acc[mi][ni], al[mi], bh0, bh1);
                }
            }
        }
        __syncthreads();
    }
    // --- epilogue: write pre-activation ---
    #pragma unroll
    for (int mi = 0; mi < 2; mi++) {
        int r0 = m0 + wm + mi * 16 + g;
        #pragma unroll
        for (int ni = 0; ni < NF; ni++) {
            int c = wn + ni * 8 + 2 * tg;
            if (r0 < M)
                *(float2*)&C[(long)r0 * BN + c] = make_float2(acc[mi][ni][0], acc[mi][ni][1]);
            if (r0 + 8 < M)
                *(float2*)&C[(long)(r0 + 8) * BN + c] = make_float2(acc[mi][ni][2], acc[mi][ni][3]);
        }
    }
}

// ---------------------------------------------------------------------------
// CSR aggregation: out[d] = b + dinv[d]*(dinv[d]*pre[d] + sum_s dinv[s]*pre[s])
// DIM=128: warp per node, float4 per lane. 2-deep software pipeline.
__global__ void k_agg128(const float* __restrict__ pre, const int* __restrict__ off,
                         const int* __restrict__ csr_src, const float* __restrict__ dinv,
                         const float* __restrict__ bias, float* __restrict__ out) {
    int t = blockIdx.x * blockDim.x + threadIdx.x;
    int node = t >> 5, lane = t & 31;
    if (node >= NN) return;
    int beg = __ldg(&off[node]), end = __ldg(&off[node + 1]);
    const float4* p4 = (const float4*)pre;
    float4 acc = make_float4(0.f, 0.f, 0.f, 0.f);
    if (beg < end) {
        int s = __ldg(&csr_src[beg]);
        float ws = __ldg(&dinv[s]);
        float4 v = __ldg(p4 + (long)s * 32 + lane);
        for (int i = beg + 1; i < end; i++) {
            int s2 = __ldg(&csr_src[i]);
            float ws2 = __ldg(&dinv[s2]);
            float4 v2 = __ldg(p4 + (long)s2 * 32 + lane);
            acc.x += ws * v.x; acc.y += ws * v.y;
            acc.z += ws * v.z; acc.w += ws * v.w;
            ws = ws2; v = v2;
        }
        acc.x += ws * v.x; acc.y += ws * v.y;
        acc.z += ws * v.z; acc.w += ws * v.w;
    }
    float wd = __ldg(&dinv[node]);
    float4 sv = __ldg(p4 + (long)node * 32 + lane);
    float4 b = __ldg((const float4*)bias + lane);
    float4 o;
    o.x = b.x + wd * (acc.x + wd * sv.x);
    o.y = b.y + wd * (acc.y + wd * sv.y);
    o.z = b.z + wd * (acc.z + wd * sv.z);
    o.w = b.w + wd * (acc.w + wd * sv.w);
    *((float4*)out + (long)node * 32 + lane) = o;
}

// DIM=64: half-warp per node, float4 per lane. 2-deep software pipeline.
// FUSED heads GEMM: headpre[node, 0:6] = feat_row @ [W_attr | W_attk]
// (node-local transform — computed from the register-resident output row).
__global__ void k_agg64h(const float* __restrict__ pre, const int* __restrict__ off,
                         const int* __restrict__ csr_src, const float* __restrict__ dinv,
                         const float* __restrict__ bias,
                         const float* __restrict__ W_attr, const float* __restrict__ W_attk,
                         float* __restrict__ out, float* __restrict__ headpre) {
    __shared__ float Ws[HH2 * 6];   // [k][c] layout
    for (int i = threadIdx.x; i < HH2 * 6; i += blockDim.x) {
        int k = i / 6, c = i % 6;
        Ws[i] = (c < 3) ? __ldg(&W_attr[k * 3 + c]) : __ldg(&W_attk[k * 3 + (c - 3)]);
    }
    __syncthreads();
    int t = blockIdx.x * blockDim.x + threadIdx.x;
    int node = t >> 4, lane = t & 15;
    if (node >= NN) return;
    int beg = __ldg(&off[node]), end = __ldg(&off[node + 1]);
    const float4* p4 = (const float4*)pre;
    float4 acc = make_float4(0.f, 0.f, 0.f, 0.f);
    if (beg < end) {
        int s = __ldg(&csr_src[beg]);
        float ws = __ldg(&dinv[s]);
        float4 v = __ldg(p4 + (long)s * 16 + lane);
        for (int i = beg + 1; i < end; i++) {
            int s2 = __ldg(&csr_src[i]);
            float ws2 = __ldg(&dinv[s2]);
            float4 v2 = __ldg(p4 + (long)s2 * 16 + lane);
            acc.x += ws * v.x; acc.y += ws * v.y;
            acc.z += ws * v.z; acc.w += ws * v.w;
            ws = ws2; v = v2;
        }
        acc.x += ws * v.x; acc.y += ws * v.y;
        acc.z += ws * v.z; acc.w += ws * v.w;
    }
    float wd = __ldg(&dinv[node]);
    float4 sv = __ldg(p4 + (long)node * 16 + lane);
    float4 b = __ldg((const float4*)bias + lane);
    float4 o;
    o.x = b.x + wd * (acc.x + wd * sv.x);
    o.y = b.y + wd * (acc.y + wd * sv.y);
    o.z = b.z + wd * (acc.z + wd * sv.z);
    o.w = b.w + wd * (acc.w + wd * sv.w);
    *((float4*)out + (long)node * 16 + lane) = o;

    // heads: this lane holds features [4*lane, 4*lane+4) of the node's row
    int k0 = lane * 4;
    float h[6];
    #pragma unroll
    for (int c = 0; c < 6; c++)
        h[c] = o.x * Ws[(k0 + 0) * 6 + c] + o.y * Ws[(k0 + 1) * 6 + c]
             + o.z * Ws[(k0 + 2) * 6 + c] + o.w * Ws[(k0 + 3) * 6 + c];
    #pragma unroll
    for (int sh = 8; sh; sh >>= 1)
        #pragma unroll
        for (int c = 0; c < 6; c++)
            h[c] += __shfl_down_sync(0xffffffffu, h[c], sh, 16);
    if (lane == 0) {
        float2* hp = (float2*)(headpre + (long)node * 6);
        hp[0] = make_float2(h[0], h[1]);
        hp[1] = make_float2(h[2], h[3]);
        hp[2] = make_float2(h[4], h[5]);
    }
}

// DIM=6 heads + fused bias + log_softmax + att outputs. Warp per node.
__global__ void k_agg6(const float* __restrict__ pre, const int* __restrict__ off,
                       const int* __restrict__ csr_src, const float* __restrict__ dinv,
                       const float* __restrict__ b_attr, const float* __restrict__ b_attk,
                       float* __restrict__ out) {
    int t = blockIdx.x * blockDim.x + threadIdx.x;
    int node = t >> 5, lane = t & 31;
    if (node >= NN) return;
    int beg = __ldg(&off[node]), end = __ldg(&off[node + 1]);
    float a[6] = {0.f, 0.f, 0.f, 0.f, 0.f, 0.f};
    for (int i = beg + lane; i < end; i += 32) {
        int s = __ldg(&csr_src[i]);
        float ws = __ldg(&dinv[s]);
        const float2* p = (const float2*)(pre + (long)s * 6);
        float2 p0 = __ldg(p), p1 = __ldg(p + 1), p2 = __ldg(p + 2);
        a[0] += ws * p0.x; a[1] += ws * p0.y;
        a[2] += ws * p1.x; a[3] += ws * p1.y;
        a[4] += ws * p2.x; a[5] += ws * p2.y;
    }
    #pragma unroll
    for (int o = 16; o; o >>= 1)
        #pragma unroll
        for (int c = 0; c < 6; c++) a[c] += __shfl_down_sync(0xffffffffu, a[c], o);
    if (lane == 0) {
        float wd = __ldg(&dinv[node]);
        const float2* p = (const float2*)(pre + (long)node * 6);
        float2 p0 = __ldg(p), p1 = __ldg(p + 1), p2 = __ldg(p + 2);
        float v0 = b_attr[0] + wd * (a[0] + wd * p0.x);
        float v1 = b_attr[1] + wd * (a[1] + wd * p0.y);
        float v2 = b_attr[2] + wd * (a[2] + wd * p1.x);
        float v3 = b_attk[0] + wd * (a[3] + wd * p1.y);
        float v4 = b_attk[1] + wd * (a[4] + wd * p2.x);
        float v5 = b_attk[2] + wd * (a[5] + wd * p2.y);
        float m = fmaxf(v0, fmaxf(v1, v2));
        float l = m + logf(expf(v0 - m) + expf(v1 - m) + expf(v2 - m));
        out[OUT_LSM + node * 3 + 0] = v0 - l;
        out[OUT_LSM + node * 3 + 1] = v1 - l;
        out[OUT_LSM + node * 3 + 2] = v2 - l;
        out[OUT_ATT + node * 3 + 0] = v3;
        out[OUT_ATT + node * 3 + 1] = v4;
        out[OUT_ATT + node * 3 + 2] = v5;
    }
}

// edge scores: res[e] = dot(feat[i], feat[j]), 8 lanes/edge
__global__ void k_edge_scores(const float* __restrict__ feat,
                              const int* __restrict__ pos,
                              const int* __restrict__ neg,
                              float* __restrict__ res) {
    int t = blockIdx.x * blockDim.x + threadIdx.x;
    int e = t >> 3, l = t & 7;
    if (e >= 2 * PEE) return;
    int a, b;
    if (e < PEE) { a = __ldg(pos + e); b = __ldg(pos + PEE + e); }
    else         { a = __ldg(neg + (e - PEE)); b = __ldg(neg + PEE + (e - PEE)); }
    const float4* fa = (const float4*)(feat + (long)a * 64);
    const float4* fb = (const float4*)(feat + (long)b * 64);
    float4 u = __ldg(fa + l), v = __ldg(fb + l);
    float s = u.x * v.x + u.y * v.y + u.z * v.z + u.w * v.w;
    u = __ldg(fa + l + 8); v = __ldg(fb + l + 8);
    s += u.x * v.x + u.y * v.y + u.z * v.z + u.w * v.w;
    s += __shfl_down_sync(0xffffffffu, s, 4, 8);
    s += __shfl_down_sync(0xffffffffu, s, 2, 8);
    s += __shfl_down_sync(0xffffffffu, s, 1, 8);
    if (l == 0) res[e] = s;
}

// ---------------------------------------------------------------------------
static inline int cdiv(long a, int b) { return (int)((a + b - 1) / b); }

extern "C" void kernel_launch(void* const* d_in, const int* in_sizes, int n_in,
                              void* d_out, int out_size) {
    const float* x      = (const float*)d_in[0];
    const float* glove  = (const float*)d_in[1];
    const float* W1     = (const float*)d_in[2];
    const float* b1     = (const float*)d_in[3];
    const float* W2     = (const float*)d_in[4];
    const float* b2     = (const float*)d_in[5];
    const float* W_attr = (const float*)d_in[6];
    const float* b_attr = (const float*)d_in[7];
    const float* W_attk = (const float*)d_in[8];
    const float* b_attk = (const float*)d_in[9];
    const int* edge     = (const int*)d_in[10];
    const int* pos      = (const int*)d_in[11];
    const int* neg      = (const int*)d_in[12];
    float* out = (float*)d_out;

    const int* e_src = edge;
    const int* e_dst = edge + EE;

    int *degi, *off, *cursor, *csr_src;
    float *dinv, *gW1, *h1pre, *h1, *h2pre, *headpre;
    __nv_bfloat16 *W1hT, *W1lT, *W2hT, *W2lT;
    cudaGetSymbolAddress((void**)&degi,    g_degi);
    cudaGetSymbolAddress((void**)&dinv,    g_dinv);
    cudaGetSymbolAddress((void**)&off,     g_off);
    cudaGetSymbolAddress((void**)&cursor,  g_cursor);
    cudaGetSymbolAddress((void**)&csr_src, g_csr_src);
    cudaGetSymbolAddress((void**)&gW1,     g_gW1);
    cudaGetSymbolAddress((void**)&W1hT,    g_W1hT);
    cudaGetSymbolAddress((void**)&W1lT,    g_W1lT);
    cudaGetSymbolAddress((void**)&W2hT,    g_W2hT);
    cudaGetSymbolAddress((void**)&W2lT,    g_W2lT);
    cudaGetSymbolAddress((void**)&h1pre,   g_h1pre);
    cudaGetSymbolAddress((void**)&h1,      g_h1);
    cudaGetSymbolAddress((void**)&h2pre,   g_h2pre);
    cudaGetSymbolAddress((void**)&headpre, g_headpre);

    float* feat = out + OUT_FEAT;

    cudaMemsetAsync(degi, 0, NN * sizeof(int));

    // GEMM1 path first (independent of graph structure)
    k_deg_acc<<<cdiv(EE, 256), 256>>>(e_dst, degi);
    k_glove_w1<<<FF, HH1>>>(glove, W1, gW1);
    k_splitW<FF, KPAD1, HH1><<<cdiv((long)HH1 * KPAD1, 256), 256>>>(gW1, W1hT, W1lT);
    k_mma<HH1, FF, KPAD1, false><<<cdiv(NN, 128), 256>>>(x, W1hT, W1lT, h1pre, NN);

    // graph structure
    k_dinv<<<cdiv(NN, 256), 256>>>(degi, dinv);
    k_scan<<<1, 1024>>>(degi, off, cursor);
    k_fill<<<cdiv(EE, 256), 256>>>(e_src, e_dst, cursor, csr_src);

    // layer 1 aggregate (bias + self-loop fused)
    k_agg128<<<cdiv((long)NN * 32, 256), 256>>>(h1pre, off, csr_src, dinv, b1, h1);

    // layer 2: relu fused into A load
    k_splitW<KPAD2, KPAD2, HH2><<<cdiv((long)HH2 * KPAD2, 256), 256>>>(W2, W2hT, W2lT);
    k_mma<HH2, HH1, KPAD2, true><<<cdiv(NN, 128), 256>>>(h1, W2hT, W2lT, h2pre, NN);

    // layer 2 aggregate + FUSED heads GEMM (headpre is node-local in feat)
    k_agg64h<<<cdiv((long)NN * 16, 256), 256>>>(h2pre, off, csr_src, dinv, b2,
                                                W_attr, W_attk, feat, headpre);

    // heads aggregate + log_softmax + att fused
    k_agg6<<<cdiv((long)NN * 32, 256), 256>>>(headpre, off, csr_src, dinv,
                                              b_attr, b_attk, out);

    // edge dot-product scores
    k_edge_scores<<<cdiv((long)2 * PEE * 8, 256), 256>>>(feat, pos, neg, out + OUT_RES);
}

// round 8
// speedup vs baseline: 1.6936x; 1.0051x over previous
#include <cuda_runtime.h>
#include <cuda_bf16.h>
#include <math.h>

// Problem constants
#define NN   50000
#define FF   500
#define EE   1600000
#define PEE  400000
#define HH1  128
#define HH2  64

// Output layout (floats): res[800000] | lsm[150000] | att[150000] | feat[3200000]
#define OUT_RES  0
#define OUT_LSM  800000
#define OUT_ATT  950000
#define OUT_FEAT 1100000

#define KPAD1 512   // 500 padded
#define KPAD2 128

// ---------------------------------------------------------------------------
// Scratch (static __device__ arrays; allocation-free per harness rules)
__device__ int   g_degi[NN];
__device__ float g_dinv[NN];
__device__ int   g_off[NN + 1];
__device__ int   g_cursor[NN];
__device__ int   g_csr_src[EE];
__device__ float g_gW1[FF * HH1];
__device__ __nv_bfloat16 g_W1hT[HH1 * KPAD1];
__device__ __nv_bfloat16 g_W1lT[HH1 * KPAD1];
__device__ __nv_bfloat16 g_W2hT[HH2 * KPAD2];
__device__ __nv_bfloat16 g_W2lT[HH2 * KPAD2];
__device__ float g_h1pre[NN * HH1];   // dinv-scaled
__device__ float g_h1[NN * HH1];
__device__ float g_h2pre[NN * HH2];   // dinv-scaled
__device__ float g_headpre[NN * 6];   // dinv-scaled

// ---------------------------------------------------------------------------
__device__ __forceinline__ unsigned pack_bf16(float a, float b) {
    __nv_bfloat162 h = __floats2bfloat162_rn(a, b);
    return *(unsigned*)&h;
}
__device__ __forceinline__ float bf_hi(float v) {
    return __bfloat162float(__float2bfloat16(v));
}
__device__ __forceinline__ void mma16816(float* d, const unsigned* a,
                                         unsigned b0, unsigned b1) {
    asm volatile(
        "mma.sync.aligned.m16n8k16.row.col.f32.bf16.bf16.f32 "
        "{%0,%1,%2,%3},{%4,%5,%6,%7},{%8,%9},{%0,%1,%2,%3};\n"
        : "+f"(d[0]), "+f"(d[1]), "+f"(d[2]), "+f"(d[3])
        : "r"(a[0]), "r"(a[1]), "r"(a[2]), "r"(a[3]), "r"(b0), "r"(b1));
}
__device__ __forceinline__ void ldsm4(unsigned* r, unsigned addr) {
    asm volatile("ldmatrix.sync.aligned.m8n8.x4.shared.b16 {%0,%1,%2,%3}, [%4];"
                 : "=r"(r[0]), "=r"(r[1]), "=r"(r[2]), "=r"(r[3]) : "r"(addr));
}
__device__ __forceinline__ void cp16(unsigned daddr, const void* sptr) {
    asm volatile("cp.async.cg.shared.global [%0], [%1], 16;"
                 :: "r"(daddr), "l"(sptr) : "memory");
}
#define CP_COMMIT() asm volatile("cp.async.commit_group;" ::: "memory")
#define CP_WAIT0()  asm volatile("cp.async.wait_group 0;" ::: "memory")

// ---------------------------------------------------------------------------
// gW1 = glove @ W1   [FF x FF] @ [FF x HH1]
__global__ void k_glove_w1(const float* __restrict__ glove,
                           const float* __restrict__ W1,
                           float* __restrict__ gW1) {
    __shared__ float row[FF];
    int k = blockIdx.x;
    for (int f = threadIdx.x; f < FF; f += blockDim.x) row[f] = glove[k * FF + f];
    __syncthreads();
    int j = threadIdx.x;  // 128 threads
    float acc = 0.f;
    #pragma unroll 4
    for (int f = 0; f < FF; f++) acc += row[f] * __ldg(&W1[f * HH1 + j]);
    gW1[k * HH1 + j] = acc;
}

// Split weight W[KS x N] into transposed bf16 hi/lo [N x KP] (zero padded)
template <int KS, int KP, int NW>
__global__ void k_splitW(const float* __restrict__ W,
                         __nv_bfloat16* __restrict__ WhT,
                         __nv_bfloat16* __restrict__ WlT) {
    int idx = blockIdx.x * blockDim.x + threadIdx.x;
    if (idx >= NW * KP) return;
    int n = idx / KP, k = idx % KP;
    float v = (k < KS) ? __ldg(&W[(long)k * NW + n]) : 0.f;
    float h = bf_hi(v);
    WhT[idx] = __float2bfloat16(h);
    WlT[idx] = __float2bfloat16(v - h);
}

// ---------------------------------------------------------------------------
// degree / norm / CSR build
__global__ void k_deg_acc(const int* __restrict__ dst, int* __restrict__ degi) {
    int e = blockIdx.x * blockDim.x + threadIdx.x;
    if (e < EE) atomicAdd(&degi[dst[e]], 1);
}
__global__ void k_dinv(const int* __restrict__ degi, float* __restrict__ dinv) {
    int i = blockIdx.x * blockDim.x + threadIdx.x;
    if (i < NN) dinv[i] = rsqrtf((float)degi[i] + 1.0f);  // +1 self loop
}
__global__ void k_scan(const int* __restrict__ degi, int* __restrict__ off,
                       int* __restrict__ cursor) {
    __shared__ int warp_sums[32];
    __shared__ int s_carry;
    int tid = threadIdx.x, lane = tid & 31, wid = tid >> 5;
    if (tid == 0) s_carry = 0;
    __syncthreads();
    for (int base = 0; base < NN; base += 1024) {
        int idx = base + tid;
        int v = (idx < NN) ? degi[idx] : 0;
        int x = v;
        #pragma unroll
        for (int o = 1; o < 32; o <<= 1) {
            int y = __shfl_up_sync(0xffffffffu, x, o);
            if (lane >= o) x += y;
        }
        if (lane == 31) warp_sums[wid] = x;
        __syncthreads();
        if (wid == 0) {
            int s = warp_sums[lane];
            #pragma unroll
            for (int o = 1; o < 32; o <<= 1) {
                int y = __shfl_up_sync(0xffffffffu, s, o);
                if (lane >= o) s += y;
            }
            warp_sums[lane] = s;
        }
        __syncthreads();
        int carry = s_carry;
        int woff = wid ? warp_sums[wid - 1] : 0;
        int excl = carry + woff + (x - v);
        if (idx < NN) { off[idx] = excl; cursor[idx] = excl; }
        __syncthreads();
        if (tid == 0) s_carry = carry + warp_sums[31];
        __syncthreads();
    }
    if (threadIdx.x == 0) off[NN] = s_carry;
}
__global__ void k_fill(const int* __restrict__ src, const int* __restrict__ dst,
                       int* __restrict__ cursor, int* __restrict__ csr_src) {
    int e = blockIdx.x * blockDim.x + threadIdx.x;
    if (e >= EE) return;
    int d = dst[e];
    int p = atomicAdd(&cursor[d], 1);
    csr_src[p] = src[e];
}

// ---------------------------------------------------------------------------
// Pipelined bf16-split tensor GEMM with ldmatrix + cp.async double buffering.
// C[M x BN] = rowscale[m] * (A[M x KSRC] @ B)  (B split hi/lo, [BN x KP])
// BM=128, BK=32, 256 threads (8 warps, 4x2 warp grid). RELU applied to A on load.
template <int BN, int KSRC, int KP, bool RELU>
__global__ void __launch_bounds__(256)
k_mma(const float* __restrict__ A,
      const __nv_bfloat16* __restrict__ BhT, const __nv_bfloat16* __restrict__ BlT,
      const float* __restrict__ rowscale, float* __restrict__ C, int M) {
    constexpr int BM = 128, BK = 32, BKP = 40;
    constexpr int WN = (BN == 128) ? 64 : 32;
    constexpr int NF = WN / 8;
    constexpr int A_SZ = BM * BKP;          // elems per A buffer
    constexpr int B_SZ = BN * BKP;
    constexpr int STAGE = 2 * A_SZ + 2 * B_SZ;
    constexpr int T = KP / BK;

    extern __shared__ __align__(16) __nv_bfloat16 sm[];
    unsigned smb = (unsigned)__cvta_generic_to_shared(sm);

    int tid = threadIdx.x;
    int m0 = blockIdx.x * BM;
    int lane = tid & 31, w = tid >> 5;
    int wm = (w >> 1) * 32, wn = (w & 1) * WN;
    int g = lane >> 2, tg = lane & 3;
    int l8 = lane & 7, sub = lane >> 3;
    // ldmatrix per-lane fragment byte offset within a buffer
    unsigned fo2 = ((((sub & 1) * 8 + l8) * BKP) + (sub >> 1) * 8) * 2;

    float acc[2][NF][4];
    #pragma unroll
    for (int mi = 0; mi < 2; mi++)
        #pragma unroll
        for (int ni = 0; ni < NF; ni++)
            #pragma unroll
            for (int q = 0; q < 4; q++) acc[mi][ni][q] = 0.f;

    int ar = tid >> 1;            // 0..127 : A staging row
    int ac0 = (tid & 1) * 16;     // column half
    long gr = m0 + ar;
    const float4* ap = (const float4*)(A + gr * (long)KSRC);

    // --- helpers -----------------------------------------------------------
    auto copyB = [&](int s, int kc) {
        unsigned bhB = smb + (s * STAGE + 2 * A_SZ) * 2;
        unsigned blB = bhB + B_SZ * 2;
        for (int idx = tid; idx < BN * 4; idx += 256) {
            int n = idx >> 2, ko = (idx & 3) * 8;
            unsigned doff = (n * BKP + ko) * 2;
            cp16(bhB + doff, BhT + (long)n * KP + kc + ko);
            cp16(blB + doff, BlT + (long)n * KP + kc + ko);
        }
    };
    auto loadA = [&](float4* pv, int kc) {
        #pragma unroll
        for (int j = 0; j < 4; j++) {
            int c = kc + ac0 + j * 4;
            float4 v = make_float4(0.f, 0.f, 0.f, 0.f);
            if (gr < M && c < KSRC) v = __ldg(ap + (c >> 2));
            if (RELU) {
                v.x = fmaxf(v.x, 0.f); v.y = fmaxf(v.y, 0.f);
                v.z = fmaxf(v.z, 0.f); v.w = fmaxf(v.w, 0.f);
            }
            pv[j] = v;
        }
    };
    auto stsA = [&](int s, const float4* pv) {
        __nv_bfloat16* AhS = sm + s * STAGE;
        __nv_bfloat16* AlS = AhS + A_SZ;
        #pragma unroll
        for (int j = 0; j < 4; j++) {
            float4 v = pv[j];
            float h0 = bf_hi(v.x), h1 = bf_hi(v.y), h2 = bf_hi(v.z), h3 = bf_hi(v.w);
            int lc = ac0 + j * 4;
            uint2 hh; hh.x = pack_bf16(h0, h1); hh.y = pack_bf16(h2, h3);
            uint2 ll; ll.x = pack_bf16(v.x - h0, v.y - h1);
            ll.y = pack_bf16(v.z - h2, v.w - h3);
            *(uint2*)(AhS + ar * BKP + lc) = hh;
            *(uint2*)(AlS + ar * BKP + lc) = ll;
        }
    };
    auto compute = [&](int s) {
        unsigned base = smb + s * STAGE * 2;
        unsigned ahB = base, alB = base + A_SZ * 2;
        unsigned bhB = base + 2 * A_SZ * 2, blB = bhB + B_SZ * 2;
        #pragma unroll
        for (int ks = 0; ks < 2; ks++) {
            int kb = ks * 16;
            unsigned ah[2][4], al[2][4];
            #pragma unroll
            for (int mi = 0; mi < 2; mi++) {
                unsigned ro = ((wm + mi * 16) * BKP + kb) * 2 + fo2;
                ldsm4(ah[mi], ahB + ro);
                ldsm4(al[mi], alB + ro);
            }
            #pragma unroll
            for (int p = 0; p < NF / 2; p++) {
                unsigned bo = ((wn + p * 16) * BKP + kb) * 2 + fo2;
                unsigned bh[4], bl[4];
                ldsm4(bh, bhB + bo);
                ldsm4(bl, blB + bo);
                #pragma unroll
                for (int mi = 0; mi < 2; mi++) {
                    mma16816(acc[mi][2 * p],     ah[mi], bh[0], bh[2]);
                    mma16816(acc[mi][2 * p],     ah[mi], bl[0], bl[2]);
                    mma16816(acc[mi][2 * p],     al[mi], bh[0], bh[2]);
                    mma16816(acc[mi][2 * p + 1], ah[mi], bh[1], bh[3]);
                    mma16816(acc[mi][2 * p + 1], ah[mi], bl[1], bl[3]);
                    mma16816(acc[mi][2 * p + 1], al[mi], bh[1], bh[3]);
                }
            }
        }
    };

    // --- prologue: fill stage 0 -------------------------------------------
    copyB(0, 0);
    CP_COMMIT();
    {
        float4 pv[4];
        loadA(pv, 0);
        stsA(0, pv);
    }

    // --- main pipeline -----------------------------------------------------
    #pragma unroll 1
    for (int i = 0; i < T; i++) {
        int s = i & 1;
        CP_WAIT0();
        __syncthreads();
        float4 pv2[4];
        if (i + 1 < T) {
            copyB(s ^ 1, (i + 1) * BK);
            CP_COMMIT();
            loadA(pv2, (i + 1) * BK);
        }
        compute(s);
        if (i + 1 < T) stsA(s ^ 1, pv2);
    }

    // --- epilogue: write rowscale * result --------------------------------
    #pragma unroll
    for (int mi = 0; mi < 2; mi++) {
        int r0 = m0 + wm + mi * 16 + g;
        float s0 = (r0 < M) ? __ldg(&rowscale[r0]) : 0.f;
        float s1 = (r0 + 8 < M) ? __ldg(&rowscale[r0 + 8]) : 0.f;
        #pragma unroll
        for (int ni = 0; ni < NF; ni++) {
            int c = wn + ni * 8 + 2 * tg;
            if (r0 < M)
                *(float2*)&C[(long)r0 * BN + c] =
                    make_float2(s0 * acc[mi][ni][0], s0 * acc[mi][ni][1]);
            if (r0 + 8 < M)
                *(float2*)&C[(long)(r0 + 8) * BN + c] =
                    make_float2(s1 * acc[mi][ni][2], s1 * acc[mi][ni][3]);
        }
    }
}

// ---------------------------------------------------------------------------
// CSR aggregation. pre rows are PRE-SCALED by dinv[src].
// out[d] = b + dinv[d]*(sum_s pre[s] + pre[d])
// DIM=128: warp per node, float4 per lane. 2-deep software pipeline.
__global__ void k_agg128(const float* __restrict__ pre, const int* __restrict__ off,
                         const int* __restrict__ csr_src, const float* __restrict__ dinv,
                         const float* __restrict__ bias, float* __restrict__ out) {
    int t = blockIdx.x * blockDim.x + threadIdx.x;
    int node = t >> 5, lane = t & 31;
    if (node >= NN) return;
    int beg = __ldg(&off[node]), end = __ldg(&off[node + 1]);
    const float4* p4 = (const float4*)pre;
    float4 acc = make_float4(0.f, 0.f, 0.f, 0.f);
    if (beg < end) {
        int s = __ldg(&csr_src[beg]);
        float4 v = __ldg(p4 + (long)s * 32 + lane);
        for (int i = beg + 1; i < end; i++) {
            int s2 = __ldg(&csr_src[i]);
            float4 v2 = __ldg(p4 + (long)s2 * 32 + lane);
            acc.x += v.x; acc.y += v.y; acc.z += v.z; acc.w += v.w;
            v = v2;
        }
        acc.x += v.x; acc.y += v.y; acc.z += v.z; acc.w += v.w;
    }
    float wd = __ldg(&dinv[node]);
    float4 sv = __ldg(p4 + (long)node * 32 + lane);
    float4 b = __ldg((const float4*)bias + lane);
    float4 o;
    o.x = b.x + wd * (acc.x + sv.x);
    o.y = b.y + wd * (acc.y + sv.y);
    o.z = b.z + wd * (acc.z + sv.z);
    o.w = b.w + wd * (acc.w + sv.w);
    *((float4*)out + (long)node * 32 + lane) = o;
}

// DIM=64: half-warp per node + FUSED heads GEMM (headpre scaled by dinv[node]).
__global__ void k_agg64h(const float* __restrict__ pre, const int* __restrict__ off,
                         const int* __restrict__ csr_src, const float* __restrict__ dinv,
                         const float* __restrict__ bias,
                         const float* __restrict__ W_attr, const float* __restrict__ W_attk,
                         float* __restrict__ out, float* __restrict__ headpre) {
    __shared__ float Ws[HH2 * 6];   // [k][c] layout
    for (int i = threadIdx.x; i < HH2 * 6; i += blockDim.x) {
        int k = i / 6, c = i % 6;
        Ws[i] = (c < 3) ? __ldg(&W_attr[k * 3 + c]) : __ldg(&W_attk[k * 3 + (c - 3)]);
    }
    __syncthreads();
    int t = blockIdx.x * blockDim.x + threadIdx.x;
    int node = t >> 4, lane = t & 15;
    if (node >= NN) return;
    int beg = __ldg(&off[node]), end = __ldg(&off[node + 1]);
    const float4* p4 = (const float4*)pre;
    float4 acc = make_float4(0.f, 0.f, 0.f, 0.f);
    if (beg < end) {
        int s = __ldg(&csr_src[beg]);
        float4 v = __ldg(p4 + (long)s * 16 + lane);
        for (int i = beg + 1; i < end; i++) {
            int s2 = __ldg(&csr_src[i]);
            float4 v2 = __ldg(p4 + (long)s2 * 16 + lane);
            acc.x += v.x; acc.y += v.y; acc.z += v.z; acc.w += v.w;
            v = v2;
        }
        acc.x += v.x; acc.y += v.y; acc.z += v.z; acc.w += v.w;
    }
    float wd = __ldg(&dinv[node]);
    float4 sv = __ldg(p4 + (long)node * 16 + lane);
    float4 b = __ldg((const float4*)bias + lane);
    float4 o;
    o.x = b.x + wd * (acc.x + sv.x);
    o.y = b.y + wd * (acc.y + sv.y);
    o.z = b.z + wd * (acc.z + sv.z);
    o.w = b.w + wd * (acc.w + sv.w);
    *((float4*)out + (long)node * 16 + lane) = o;

    // heads: this lane holds features [4*lane, 4*lane+4) of the node's row
    int k0 = lane * 4;
    float h[6];
    #pragma unroll
    for (int c = 0; c < 6; c++)
        h[c] = o.x * Ws[(k0 + 0) * 6 + c] + o.y * Ws[(k0 + 1) * 6 + c]
             + o.z * Ws[(k0 + 2) * 6 + c] + o.w * Ws[(k0 + 3) * 6 + c];
    #pragma unroll
    for (int sh = 8; sh; sh >>= 1)
        #pragma unroll
        for (int c = 0; c < 6; c++)
            h[c] += __shfl_down_sync(0xffffffffu, h[c], sh, 16);
    if (lane == 0) {
        float2* hp = (float2*)(headpre + (long)node * 6);
        hp[0] = make_float2(wd * h[0], wd * h[1]);
        hp[1] = make_float2(wd * h[2], wd * h[3]);
        hp[2] = make_float2(wd * h[4], wd * h[5]);
    }
}

// DIM=6 heads + fused bias + log_softmax + att. pre rows pre-scaled.
__global__ void k_agg6(const float* __restrict__ pre, const int* __restrict__ off,
                       const int* __restrict__ csr_src, const float* __restrict__ dinv,
                       const float* __restrict__ b_attr, const float* __restrict__ b_attk,
                       float* __restrict__ out) {
    int t = blockIdx.x * blockDim.x + threadIdx.x;
    int node = t >> 5, lane = t & 31;
    if (node >= NN) return;
    int beg = __ldg(&off[node]), end = __ldg(&off[node + 1]);
    float a[6] = {0.f, 0.f, 0.f, 0.f, 0.f, 0.f};
    for (int i = beg + lane; i < end; i += 32) {
        int s = __ldg(&csr_src[i]);
        const float2* p = (const float2*)(pre + (long)s * 6);
        float2 p0 = __ldg(p), p1 = __ldg(p + 1), p2 = __ldg(p + 2);
        a[0] += p0.x; a[1] += p0.y;
        a[2] += p1.x; a[3] += p1.y;
        a[4] += p2.x; a[5] += p2.y;
    }
    #pragma unroll
    for (int o = 16; o; o >>= 1)
        #pragma unroll
        for (int c = 0; c < 6; c++) a[c] += __shfl_down_sync(0xffffffffu, a[c], o);
    if (lane == 0) {
        float wd = __ldg(&dinv[node]);
        const float2* p = (const float2*)(pre + (long)node * 6);
        float2 p0 = __ldg(p), p1 = __ldg(p + 1), p2 = __ldg(p + 2);
        float v0 = b_attr[0] + wd * (a[0] + p0.x);
        float v1 = b_attr[1] + wd * (a[1] + p0.y);
        float v2 = b_attr[2] + wd * (a[2] + p1.x);
        float v3 = b_attk[0] + wd * (a[3] + p1.y);
        float v4 = b_attk[1] + wd * (a[4] + p2.x);
        float v5 = b_attk[2] + wd * (a[5] + p2.y);
        float m = fmaxf(v0, fmaxf(v1, v2));
        float l = m + logf(expf(v0 - m) + expf(v1 - m) + expf(v2 - m));
        out[OUT_LSM + node * 3 + 0] = v0 - l;
        out[OUT_LSM + node * 3 + 1] = v1 - l;
        out[OUT_LSM + node * 3 + 2] = v2 - l;
        out[OUT_ATT + node * 3 + 0] = v3;
        out[OUT_ATT + node * 3 + 1] = v4;
        out[OUT_ATT + node * 3 + 2] = v5;
    }
}

// edge scores: res[e] = dot(feat[i], feat[j]), 8 lanes/edge
__global__ void k_edge_scores(const float* __restrict__ feat,
                              const int* __restrict__ pos,
                              const int* __restrict__ neg,
                              float* __restrict__ res) {
    int t = blockIdx.x * blockDim.x + threadIdx.x;
    int e = t >> 3, l = t & 7;
    if (e >= 2 * PEE) return;
    int a, b;
    if (e < PEE) { a = __ldg(pos + e); b = __ldg(pos + PEE + e); }
    else         { a = __ldg(neg + (e - PEE)); b = __ldg(neg + PEE + (e - PEE)); }
    const float4* fa = (const float4*)(feat + (long)a * 64);
    const float4* fb = (const float4*)(feat + (long)b * 64);
    float4 u = __ldg(fa + l), v = __ldg(fb + l);
    float s = u.x * v.x + u.y * v.y + u.z * v.z + u.w * v.w;
    u = __ldg(fa + l + 8); v = __ldg(fb + l + 8);
    s += u.x * v.x + u.y * v.y + u.z * v.z + u.w * v.w;
    s += __shfl_down_sync(0xffffffffu, s, 4, 8);
    s += __shfl_down_sync(0xffffffffu, s, 2, 8);
    s += __shfl_down_sync(0xffffffffu, s, 1, 8);
    if (l == 0) res[e] = s;
}

// ---------------------------------------------------------------------------
static inline int cdiv(long a, int b) { return (int)((a + b - 1) / b); }

// dynamic smem: (2*A + 2*B) per stage * 2 stages * 2 bytes
#define SMEM1 ((2 * 128 * 40 + 2 * 128 * 40) * 2 * 2)   // 81920
#define SMEM2 ((2 * 128 * 40 + 2 * 64 * 40) * 2 * 2)    // 61440

extern "C" void kernel_launch(void* const* d_in, const int* in_sizes, int n_in,
                              void* d_out, int out_size) {
    const float* x      = (const float*)d_in[0];
    const float* glove  = (const float*)d_in[1];
    const float* W1     = (const float*)d_in[2];
    const float* b1     = (const float*)d_in[3];
    const float* W2     = (const float*)d_in[4];
    const float* b2     = (const float*)d_in[5];
    const float* W_attr = (const float*)d_in[6];
    const float* b_attr = (const float*)d_in[7];
    const float* W_attk = (const float*)d_in[8];
    const float* b_attk = (const float*)d_in[9];
    const int* edge     = (const int*)d_in[10];
    const int* pos      = (const int*)d_in[11];
    const int* neg      = (const int*)d_in[12];
    float* out = (float*)d_out;

    const int* e_src = edge;
    const int* e_dst = edge + EE;

    int *degi, *off, *cursor, *csr_src;
    float *dinv, *gW1, *h1pre, *h1, *h2pre, *headpre;
    __nv_bfloat16 *W1hT, *W1lT, *W2hT, *W2lT;
    cudaGetSymbolAddress((void**)&degi,    g_degi);
    cudaGetSymbolAddress((void**)&dinv,    g_dinv);
    cudaGetSymbolAddress((void**)&off,     g_off);
    cudaGetSymbolAddress((void**)&cursor,  g_cursor);
    cudaGetSymbolAddress((void**)&csr_src, g_csr_src);
    cudaGetSymbolAddress((void**)&gW1,     g_gW1);
    cudaGetSymbolAddress((void**)&W1hT,    g_W1hT);
    cudaGetSymbolAddress((void**)&W1lT,    g_W1lT);
    cudaGetSymbolAddress((void**)&W2hT,    g_W2hT);
    cudaGetSymbolAddress((void**)&W2lT,    g_W2lT);
    cudaGetSymbolAddress((void**)&h1pre,   g_h1pre);
    cudaGetSymbolAddress((void**)&h1,      g_h1);
    cudaGetSymbolAddress((void**)&h2pre,   g_h2pre);
    cudaGetSymbolAddress((void**)&headpre, g_headpre);

    float* feat = out + OUT_FEAT;

    cudaFuncSetAttribute(k_mma<HH1, FF, KPAD1, false>,
                         cudaFuncAttributeMaxDynamicSharedMemorySize, SMEM1);
    cudaFuncSetAttribute(k_mma<HH2, HH1, KPAD2, true>,
                         cudaFuncAttributeMaxDynamicSharedMemorySize, SMEM2);

    cudaMemsetAsync(degi, 0, NN * sizeof(int));

    // degree/dinv first (GEMM epilogues consume dinv)
    k_deg_acc<<<cdiv(EE, 256), 256>>>(e_dst, degi);
    k_dinv<<<cdiv(NN, 256), 256>>>(degi, dinv);

    // weights prep
    k_glove_w1<<<FF, HH1>>>(glove, W1, gW1);
    k_splitW<FF, KPAD1, HH1><<<cdiv((long)HH1 * KPAD1, 256), 256>>>(gW1, W1hT, W1lT);

    // GEMM1: h1pre = dinv .* (x @ gW1)
    k_mma<HH1, FF, KPAD1, false><<<cdiv(NN, 128), 256, SMEM1>>>(x, W1hT, W1lT,
                                                                dinv, h1pre, NN);

    // CSR build
    k_scan<<<1, 1024>>>(degi, off, cursor);
    k_fill<<<cdiv(EE, 256), 256>>>(e_src, e_dst, cursor, csr_src);

    // layer 1 aggregate (bias + self-loop fused; rows pre-scaled)
    k_agg128<<<cdiv((long)NN * 32, 256), 256>>>(h1pre, off, csr_src, dinv, b1, h1);

    // GEMM2: h2pre = dinv .* (relu(h1) @ W2)
    k_splitW<KPAD2, KPAD2, HH2><<<cdiv((long)HH2 * KPAD2, 256), 256>>>(W2, W2hT, W2lT);
    k_mma<HH2, HH1, KPAD2, true><<<cdiv(NN, 128), 256, SMEM2>>>(h1, W2hT, W2lT,
                                                                dinv, h2pre, NN);

    // layer 2 aggregate + FUSED heads GEMM (headpre dinv-scaled on write)
    k_agg64h<<<cdiv((long)NN * 16, 256), 256>>>(h2pre, off, csr_src, dinv, b2,
                                                W_attr, W_attk, feat, headpre);

    // heads aggregate + log_softmax + att fused
    k_agg6<<<cdiv((long)NN * 32, 256), 256>>>(headpre, off, csr_src, dinv,
                                              b_attr, b_attk, out);

    // edge dot-product scores
    k_edge_scores<<<cdiv((long)2 * PEE * 8, 256), 256>>>(feat, pos, neg, out + OUT_RES);
}